// round 17
// baseline (speedup 1.0000x reference)
#include <cuda_runtime.h>
#include <cstdint>

// Micromagnetic LLG RK4 solver — Round 17: R16 (fused-signal, single-sim
// relax, tag-in-.w neighbor sync) + smem-op diet:
//  (a) even-stage centers (u1/u3 at own row RE) are kept in registers —
//      they are computed by the SAME thread in the preceding odd stage
//      (RA=2-ty covers RE for ty0, RB=4-ty for ty1) — removing 2 LDS.128
//      per sim-step and a 29-cyc LDS from each even stage's critical path;
//  (b) odd stages load the shared middle row (3-ty = RA's S = RB's N) once
//      instead of twice — removing 2 more LDS.128 per sim-step.
// Sum order (N+S+W+E) and all values bitwise identical to R16.
// 128 CTAs x 512 threads; CTA r owns global rows {2r,2r+1}; thread
// (ty = tid>>8, c = tid&255) owns cell (2r+ty, c) in both sims.

#define NXg 256
#define NYg 256
#define PLANE (NXg * NYg)
#define TSTEPS 256
#define NSRC 3
#define NPROBE 5
#define RELAXN 100
#define NBLK 128
#define NT 512
#define SROW 258
#define RBY 4128                  // row bytes = SROW * 16
#define BUFB (6 * RBY)            // per-buffer bytes (6 rows)
#define SIGB (3 * BUFB)           // per-sig smem block (3 buffers)
#define SMEM_BYTES (2 * SIGB)     // 148,608 B

__device__ float4 g_mbuf[2][2][PLANE];   // [parity][sig]
__device__ float4 g_u2[2][PLANE];        // [sig]
__device__ unsigned g_base[NBLK * 8];    // [8r]=m count, [8r+1]=u2 count

__device__ __forceinline__ float4 ldcg4(const float4* p) {
    float4 v;
    asm volatile("ld.global.cg.v4.f32 {%0,%1,%2,%3}, [%4];"
                 : "=f"(v.x), "=f"(v.y), "=f"(v.z), "=f"(v.w)
                 : "l"(p) : "memory");
    return v;
}
__device__ __forceinline__ void stcg4(float4* p, float4 v) {
    asm volatile("st.global.cg.v4.f32 [%0], {%1,%2,%3,%4};"
                 :: "l"(p), "f"(v.x), "f"(v.y), "f"(v.z), "f"(v.w)
                 : "memory");
}
__device__ __forceinline__ void lds3(float& x, float& y, float& z,
                                     uint32_t a) {
    float w_;
    asm volatile("ld.shared.v4.f32 {%0,%1,%2,%3}, [%4];"
                 : "=f"(x), "=f"(y), "=f"(z), "=f"(w_) : "r"(a));
}
__device__ __forceinline__ void sts3(uint32_t a, float x, float y, float z) {
    asm volatile("st.shared.v4.f32 [%0], {%1,%2,%3,%4};"
                 :: "r"(a), "f"(x), "f"(y), "f"(z), "f"(0.0f));
}

__device__ __forceinline__ float3 lap_torque(
    float ux, float uy, float uz,
    float sx, float sy, float sz,          // N+S+W+E sums
    float bx, float by, float bz_,         // bz_ already includes source
    float CEx, float CD, float alpha, float inv)
{
    float lx = sx - 4.0f * ux, ly = sy - 4.0f * uy, lz = sz - 4.0f * uz;
    float Bx = bx + CEx * lx;
    float By = by + CEx * ly;
    float Bz = bz_ + CEx * lz - CD * uz;
    float c1x = uy * Bz - uz * By;
    float c1y = uz * Bx - ux * Bz;
    float c1z = ux * By - uy * Bx;
    float c2x = uy * c1z - uz * c1y;
    float c2y = uz * c1x - ux * c1z;
    float c2z = ux * c1y - uy * c1x;
    const float CS = 1.0e-4f;
    float3 t;
    t.x = -inv * (c1x + alpha * c2x) + CS * (ux * uy);
    t.y = -inv * (c1y + alpha * c2y) + CS * (-(uz * uz + ux * ux));
    t.z = -inv * (c1z + alpha * c2z) + CS * (uy * uz);
    return t;
}

// Torque with N/S loaded from AC+-RBY (buffer offset BO), center passed.
#define TORQ(AC, AW, AE, BO, cx, cy, cz, bx_, by_, bz_, KV)                    \
  { float n1x, n1y, n1z, n2x, n2y, n2z, wx_, wy_, wz_, ex_, ey_, ez_;          \
    lds3(n1x, n1y, n1z, (AC) + (BO) - RBY);                                    \
    lds3(n2x, n2y, n2z, (AC) + (BO) + RBY);                                    \
    lds3(wx_, wy_, wz_, (AW) + (BO));                                          \
    lds3(ex_, ey_, ez_, (AE) + (BO));                                          \
    KV = lap_torque(cx, cy, cz,                                                \
        n1x + n2x + wx_ + ex_, n1y + n2y + wy_ + ey_, n1z + n2z + wz_ + ez_,   \
        bx_, by_, bz_, CEx, CD, alpha, inv); }

// Odd-stage pair: rows RA (N=row RA-1, S=shared mid) and RB (N=shared mid,
// S=row RB+1). Shared mid loaded once. Same sum order as TORQ (N+S+W+E).
#define TORQPAIR(BO, s, cAx_, cAy_, cAz_, cBx_, cBy_, cBz_, KA, KB)            \
  { float msx, msy, msz, nax, nay, naz, nbx, nby, nbz;                         \
    float wx_, wy_, wz_, ex_, ey_, ez_;                                        \
    lds3(msx, msy, msz, aRA + (s) * SIGB + (BO) + RBY);   /* row 3-ty */       \
    lds3(nax, nay, naz, aRA + (s) * SIGB + (BO) - RBY);                        \
    lds3(wx_, wy_, wz_, aRAw + (s) * SIGB + (BO));                             \
    lds3(ex_, ey_, ez_, aRAe + (s) * SIGB + (BO));                             \
    KA = lap_torque(cAx_, cAy_, cAz_,                                          \
        nax + msx + wx_ + ex_, nay + msy + wy_ + ey_, naz + msz + wz_ + ez_,   \
        bxA, byA, bzallA[s], CEx, CD, alpha, inv);                             \
    lds3(nbx, nby, nbz, aRB_ + (s) * SIGB + (BO) + RBY);                       \
    lds3(wx_, wy_, wz_, aRBw + (s) * SIGB + (BO));                             \
    lds3(ex_, ey_, ez_, aRBe + (s) * SIGB + (BO));                             \
    KB = lap_torque(cBx_, cBy_, cBz_,                                          \
        msx + nbx + wx_ + ex_, msy + nby + wy_ + ey_, msz + nbz + wz_ + ez_,   \
        bxB, byB, bzallB[s], CEx, CD, alpha, inv); }

// One RK4 step advancing NS sims (NS = 1 or 2, compile-time).
#define STEPK(NS)                                                              \
 { float4 v0[2], v2[2];                                                        \
   { const float4* mb = g_mbuf[ms & 1u][0];                                    \
     bool ok;                                                                  \
     do {                                                                      \
       ok = true;                                                              \
       _Pragma("unroll")                                                       \
       for (int s = 0; s < (NS); s++) {                                        \
         v0[s] = ldcg4(mb + s * PLANE + cH0);                                  \
         v2[s] = ldcg4(mb + s * PLANE + cH4);                                  \
         ok &= (((int)(__float_as_int(v0[s].w) - (int)ms) |                    \
                 (int)(__float_as_int(v2[s].w) - (int)ms)) >= 0);              \
       }                                                                       \
     } while (!ok); }                                                          \
   _Pragma("unroll")                                                           \
   for (int s = 0; s < (NS); s++) {                                            \
     sts3(aH0 + s * SIGB, v0[s].x, v0[s].y, v0[s].z);                          \
     sts3(aH4 + s * SIGB, v2[s].x, v2[s].y, v2[s].z);                          \
     sts3(aRE + s * SIGB, mox[s], moy[s], moz[s]);                             \
   }                                                                           \
   __syncthreads();                                                            \
   /* stage 1: rows RA, RB from buf0; keep u1 at RE in regs */                 \
   float cAx[2], cAy[2], cAz[2], cBx[2], cBy[2], cBz[2];                       \
   float ax[2], ay[2], az[2];                                                  \
   float uEx[2], uEy[2], uEz[2];                                               \
   _Pragma("unroll")                                                           \
   for (int s = 0; s < (NS); s++) {                                            \
     cAx[s] = ty ? v0[s].x : mox[s]; cAy[s] = ty ? v0[s].y : moy[s];           \
     cAz[s] = ty ? v0[s].z : moz[s];                                           \
     cBx[s] = ty ? mox[s] : v2[s].x; cBy[s] = ty ? moy[s] : v2[s].y;           \
     cBz[s] = ty ? moz[s] : v2[s].z;                                           \
     float3 kA, kB;                                                            \
     TORQPAIR(0, s, cAx[s], cAy[s], cAz[s], cBx[s], cBy[s], cBz[s], kA, kB);   \
     float u1Ax = cAx[s] + h2 * kA.x, u1Ay = cAy[s] + h2 * kA.y,               \
           u1Az = cAz[s] + h2 * kA.z;                                          \
     sts3(aRA + s * SIGB + BUFB, u1Ax, u1Ay, u1Az);                            \
     float u1Bx = cBx[s] + h2 * kB.x, u1By = cBy[s] + h2 * kB.y,               \
           u1Bz = cBz[s] + h2 * kB.z;                                          \
     sts3(aRB_ + s * SIGB + BUFB, u1Bx, u1By, u1Bz);                           \
     uEx[s] = ty ? u1Bx : u1Ax; uEy[s] = ty ? u1By : u1Ay;                     \
     uEz[s] = ty ? u1Bz : u1Az;                                                \
     ax[s] = ty ? kB.x : kA.x; ay[s] = ty ? kB.y : kA.y;                       \
     az[s] = ty ? kB.z : kA.z;                                                 \
   }                                                                           \
   __syncthreads();                                                            \
   /* stage 2: own row RE, center from regs; tagged u2 publish */              \
   us++;                                                                       \
   float u2x[2], u2y[2], u2z[2];                                               \
   _Pragma("unroll")                                                           \
   for (int s = 0; s < (NS); s++) {                                            \
     float3 k2;                                                                \
     TORQ(aRE + s * SIGB, aREw + s * SIGB, aREe + s * SIGB, BUFB,              \
          uEx[s], uEy[s], uEz[s], bxE, byE, bzallE[s], k2);                    \
     ax[s] += 2.0f * k2.x; ay[s] += 2.0f * k2.y; az[s] += 2.0f * k2.z;         \
     u2x[s] = mox[s] + h2 * k2.x; u2y[s] = moy[s] + h2 * k2.y;                 \
     u2z[s] = moz[s] + h2 * k2.z;                                              \
     stcg4(&g_u2[s][gcown], make_float4(u2x[s], u2y[s], u2z[s],                \
                                        __int_as_float((int)us)));             \
     sts3(aRE + s * SIGB + 2 * BUFB, u2x[s], u2y[s], u2z[s]);                  \
   }                                                                           \
   float4 w0[2], w2[2];                                                        \
   { bool ok;                                                                  \
     do {                                                                      \
       ok = true;                                                              \
       _Pragma("unroll")                                                       \
       for (int s = 0; s < (NS); s++) {                                        \
         w0[s] = ldcg4(&g_u2[s][cH0]);                                         \
         w2[s] = ldcg4(&g_u2[s][cH4]);                                         \
         ok &= (((int)(__float_as_int(w0[s].w) - (int)us) |                    \
                 (int)(__float_as_int(w2[s].w) - (int)us)) >= 0);              \
       }                                                                       \
     } while (!ok); }                                                          \
   _Pragma("unroll")                                                           \
   for (int s = 0; s < (NS); s++) {                                            \
     sts3(aH0 + s * SIGB + 2 * BUFB, w0[s].x, w0[s].y, w0[s].z);               \
     sts3(aH4 + s * SIGB + 2 * BUFB, w2[s].x, w2[s].y, w2[s].z);               \
   }                                                                           \
   __syncthreads();                                                            \
   /* stage 3: rows RA, RB from buf2; keep u3 at RE in regs */                 \
   _Pragma("unroll")                                                           \
   for (int s = 0; s < (NS); s++) {                                            \
     float dAx = ty ? w0[s].x : u2x[s], dAy = ty ? w0[s].y : u2y[s],           \
           dAz = ty ? w0[s].z : u2z[s];                                        \
     float dBx = ty ? u2x[s] : w2[s].x, dBy = ty ? u2y[s] : w2[s].y,           \
           dBz = ty ? u2z[s] : w2[s].z;                                        \
     float3 kA, kB;                                                            \
     TORQPAIR(2 * BUFB, s, dAx, dAy, dAz, dBx, dBy, dBz, kA, kB);              \
     float u3Ax = cAx[s] + hh * kA.x, u3Ay = cAy[s] + hh * kA.y,               \
           u3Az = cAz[s] + hh * kA.z;                                          \
     sts3(aRA + s * SIGB + BUFB, u3Ax, u3Ay, u3Az);                            \
     float u3Bx = cBx[s] + hh * kB.x, u3By = cBy[s] + hh * kB.y,               \
           u3Bz = cBz[s] + hh * kB.z;                                          \
     sts3(aRB_ + s * SIGB + BUFB, u3Bx, u3By, u3Bz);                           \
     uEx[s] = ty ? u3Bx : u3Ax; uEy[s] = ty ? u3By : u3Ay;                     \
     uEz[s] = ty ? u3Bz : u3Az;                                                \
     ax[s] += 2.0f * (ty ? kB.x : kA.x);                                       \
     ay[s] += 2.0f * (ty ? kB.y : kA.y);                                       \
     az[s] += 2.0f * (ty ? kB.z : kA.z);                                       \
   }                                                                           \
   __syncthreads();                                                            \
   /* stage 4: own row RE, center from regs; combine + tagged m publish */     \
   ms++;                                                                       \
   { float4* mbn = g_mbuf[ms & 1u][0];                                         \
     _Pragma("unroll")                                                         \
     for (int s = 0; s < (NS); s++) {                                          \
       float3 k4;                                                              \
       TORQ(aRE + s * SIGB, aREw + s * SIGB, aREe + s * SIGB, BUFB,            \
            uEx[s], uEy[s], uEz[s], bxE, byE, bzallE[s], k4);                  \
       ax[s] += k4.x; ay[s] += k4.y; az[s] += k4.z;                            \
       mox[s] += h6 * ax[s]; moy[s] += h6 * ay[s]; moz[s] += h6 * az[s];       \
       stcg4(mbn + s * PLANE + gcown,                                          \
             make_float4(mox[s], moy[s], moz[s], __int_as_float((int)ms)));    \
     } } }

__global__ void __launch_bounds__(NT, 1)
mm_kernel(const float* __restrict__ sig, const float* __restrict__ Bext,
          const float* __restrict__ MsatP, const int* __restrict__ srcP,
          const int* __restrict__ probeP, const int* __restrict__ finalP,
          float* __restrict__ out)
{
    extern __shared__ float4 smf4[];
    uint32_t S;
    asm("{ .reg .u64 t; cvta.to.shared.u64 t, %1; cvt.u32.u64 %0, t; }"
        : "=r"(S) : "l"(smf4));

    const int tid = threadIdx.x;
    const int c   = tid & 255;
    const int ty  = tid >> 8;               // 0/1, warp-uniform
    const int r   = blockIdx.x;

    // Smem addresses (sig-0 block; sig-1 adds compile-time SIGB).
    const uint32_t cB = (uint32_t)(c + 1) * 16u;
    const int wD = (c == 0) ? 0 : -16;
    const int eD = (c == 255) ? 0 : 16;
    const uint32_t aRA  = S + (uint32_t)(2 - ty) * RBY + cB;
    const uint32_t aRB_ = S + (uint32_t)(4 - ty) * RBY + cB;
    const uint32_t aRE  = S + (uint32_t)(2 + ty) * RBY + cB;
    const uint32_t aRAw = aRA + wD,  aRAe = aRA + eD;
    const uint32_t aRBw = aRB_ + wD, aRBe = aRB_ + eD;
    const uint32_t aREw = aRE + wD,  aREe = aRE + eD;
    const uint32_t aH0  = S + (uint32_t)ty * RBY + cB;
    const uint32_t aH4  = S + (uint32_t)(4 + ty) * RBY + cB;

    // Global rows (clamped) and poll/publish cells.
    int g;
    g = 2 * r - 2 + ty;                 // window row ty (low poll)
    const int gH0 = g < 0 ? 0 : g;
    g = 2 * r + 2 + ty;                 // window row 4+ty (high poll)
    const int gH4 = g > NXg - 1 ? NXg - 1 : g;
    g = 2 * r - ty;                     // row RA -> global
    const int gRA = g < 0 ? 0 : (g > NXg - 1 ? NXg - 1 : g);
    g = 2 * r + 2 - ty;                 // row RB -> global
    const int gRB = g < 0 ? 0 : (g > NXg - 1 ? NXg - 1 : g);
    const int gRE = 2 * r + ty;         // own row
    const int cH0 = gH0 * NYg + c;
    const int cH4 = gH4 * NYg + c;
    const int gcown = gRE * NYg + c;

    // Tag bases (own sector; persisted; uniform across CTAs).
    unsigned ms = g_base[8 * r];
    unsigned us = g_base[8 * r + 1];

    const float Msat = *MsatP;
    const float CEx = (float)(2.0 * 3.5e-12 / ((double)Msat * (5e-8 * 5e-8)));
    const float CD  = (float)(4e-7 * 3.14159265358979323846 * (double)Msat);
    const float hh  = (float)(175950000000.0 * 5e-12);   // GAMMA_LL * DT
    const float h2  = 0.5f * hh;
    const float h6  = hh * (1.0f / 6.0f);
    const int final_board = *finalP;

    // B_ext at rows RA, RB, RE (shared by both sims).
    const int oRA = gRA * NYg + c, oRB = gRB * NYg + c;
    const float bxA = __ldg(Bext + 0 * PLANE + oRA);
    const float byA = __ldg(Bext + 1 * PLANE + oRA);
    const float bzA = __ldg(Bext + 2 * PLANE + oRA);
    const float bxB = __ldg(Bext + 0 * PLANE + oRB);
    const float byB = __ldg(Bext + 1 * PLANE + oRB);
    const float bzB = __ldg(Bext + 2 * PLANE + oRB);
    const float bxE = __ldg(Bext + 0 * PLANE + gcown);
    const float byE = __ldg(Bext + 1 * PLANE + gcown);
    const float bzE = __ldg(Bext + 2 * PLANE + gcown);

    // Source ids at rows RA, RB, RE.
    int sidA, sidB, sidE;
    {
        int s0r = srcP[0], s0c = srcP[1];
        int s1r = srcP[2], s1c = srcP[3];
        int s2r = srcP[4], s2c = srcP[5];
        sidA = (gRA == s0r && c == s0c) ? 0 : (gRA == s1r && c == s1c) ? 1 :
               (gRA == s2r && c == s2c) ? 2 : -1;
        sidB = (gRB == s0r && c == s0c) ? 0 : (gRB == s1r && c == s1c) ? 1 :
               (gRB == s2r && c == s2c) ? 2 : -1;
        sidE = (gRE == s0r && c == s0c) ? 0 : (gRE == s1r && c == s1c) ? 1 :
               (gRE == s2r && c == s2c) ? 2 : -1;
    }
    // Probe id at owned cell.
    int pid = -1;
    #pragma unroll
    for (int k = 0; k < NPROBE; k++)
        if (probeP[2 * k] == gRE && probeP[2 * k + 1] == c) pid = k;

    float mox[2], moy[2], moz[2];          // own m (slot 0 used in relax)
    float bzallA[2], bzallB[2], bzallE[2]; // bz + source per sim

    // ---- init: m0 = (0,1,0); tagged publish (sig 0 only) ----
    mox[0] = 0.0f; moy[0] = 1.0f; moz[0] = 0.0f;
    ms++;
    stcg4(g_mbuf[ms & 1u][0] + gcown,
          make_float4(0.0f, 1.0f, 0.0f, __int_as_float((int)ms)));

    // ---- relax phase: alpha = 0.5, no source, SINGLE sim ----
    {
        const float alpha = 0.5f;
        const float inv = 1.0f / (1.0f + alpha * alpha);
        bzallA[0] = bzA; bzallB[0] = bzB; bzallE[0] = bzE;
        for (int s_ = 0; s_ < RELAXN; s_++) {
            STEPK(1);
        }
    }
    const float mrz = moz[0];   // m_relaxed z (own cell)

    // ---- transition: bring sig 1 online at m_relaxed, tag ms ----
    mox[1] = mox[0]; moy[1] = moy[0]; moz[1] = moz[0];
    stcg4(g_mbuf[ms & 1u][1] + gcown,
          make_float4(mox[1], moy[1], moz[1], __int_as_float((int)ms)));

    // ---- driven phase: alpha = 0.01, both signals in lockstep ----
    {
        const float alpha = 0.01f;
        const float inv = 1.0f / (1.0f + alpha * alpha);
        for (int t = 0; t < TSTEPS; t++) {
            #pragma unroll
            for (int s = 0; s < 2; s++) {
                const float* sp = sig + (s * TSTEPS + t) * NSRC;
                float sv0 = __ldg(sp + 0), sv1 = __ldg(sp + 1),
                      sv2 = __ldg(sp + 2);
                bzallA[s] = bzA + ((sidA == 0) ? sv0 : (sidA == 1) ? sv1 :
                                   (sidA == 2) ? sv2 : 0.0f);
                bzallB[s] = bzB + ((sidB == 0) ? sv0 : (sidB == 1) ? sv1 :
                                   (sidB == 2) ? sv2 : 0.0f);
                bzallE[s] = bzE + ((sidE == 0) ? sv0 : (sidE == 1) ? sv1 :
                                   (sidE == 2) ? sv2 : 0.0f);
            }
            STEPK(2);
            if (pid >= 0) {
                #pragma unroll
                for (int s = 0; s < 2; s++) {
                    float val = final_board ? (moz[s] - mrz) * Msat : moz[s];
                    out[(s * TSTEPS + t) * NPROBE + pid] = val;
                }
            }
        }
    }

    // Persist tag bases for the next graph replay (own slot only).
    if (tid == 0) {
        g_base[8 * r]     = ms;
        g_base[8 * r + 1] = us;
    }
}

extern "C" void kernel_launch(void* const* d_in, const int* in_sizes, int n_in,
                              void* d_out, int out_size) {
    const float* sig    = (const float*)d_in[0];  // (2, 256, 3)
    const float* Bext   = (const float*)d_in[1];  // (1, 3, 256, 256)
    const float* MsatP  = (const float*)d_in[2];  // scalar
    const int*   srcP   = (const int*)d_in[3];    // (3, 2)
    const int*   probeP = (const int*)d_in[4];    // (5, 2)
    const int*   finalP = (const int*)d_in[5];    // scalar
    float* out = (float*)d_out;                   // (2, 256, 5)
    (void)in_sizes; (void)n_in; (void)out_size;

    cudaFuncSetAttribute(mm_kernel,
                         cudaFuncAttributeMaxDynamicSharedMemorySize,
                         SMEM_BYTES);
    mm_kernel<<<NBLK, NT, SMEM_BYTES>>>(sig, Bext, MsatP, srcP, probeP,
                                        finalP, out);
}